// round 4
// baseline (speedup 1.0000x reference)
#include <cuda_runtime.h>
#include <cuda_fp16.h>
#include <mma.h>

using namespace nvcuda;

#define D_MODEL 1024
#define NH      16
#define DH      64
#define BATCH   4
#define SEQ     2048
#define M_TOT   (BATCH * SEQ)   // 8192

// ---------------- device scratch (no allocs allowed) ----------------
__device__ __half g_xq[(size_t)M_TOT * D_MODEL];
__device__ __half g_xk[(size_t)M_TOT * D_MODEL];
__device__ __half g_xv[(size_t)M_TOT * D_MODEL];
__device__ __half g_Wq[(size_t)D_MODEL * D_MODEL];
__device__ __half g_Wk[(size_t)D_MODEL * D_MODEL];
__device__ __half g_Wv[(size_t)D_MODEL * D_MODEL];
__device__ __half g_Wo[(size_t)D_MODEL * D_MODEL];
__device__ __half g_Q[(size_t)M_TOT * D_MODEL];   // [B*H][S][DH]
__device__ __half g_K[(size_t)M_TOT * D_MODEL];   // [B*H][S][DH]
__device__ __half g_V[(size_t)M_TOT * D_MODEL];   // [B*H][S][DH]
__device__ __half g_ctx[(size_t)M_TOT * D_MODEL]; // [B*S][H*DH]

// ---------------- fp32 -> fp16 conversion (x and W) ----------------
__global__ void __launch_bounds__(256) cvt_all(
    const float* __restrict__ xq, const float* __restrict__ xk, const float* __restrict__ xv,
    const float* __restrict__ wq, const float* __restrict__ wk,
    const float* __restrict__ wv, const float* __restrict__ wo)
{
    size_t i = (size_t)blockIdx.x * blockDim.x + threadIdx.x;
    if (i < (size_t)D_MODEL * D_MODEL) {
        g_Wq[i] = __float2half_rn(wq[i]);
        g_Wk[i] = __float2half_rn(wk[i]);
        g_Wv[i] = __float2half_rn(wv[i]);
        g_Wo[i] = __float2half_rn(wo[i]);
    }
    if (i < (size_t)M_TOT * D_MODEL) {
        g_xq[i] = __float2half_rn(xq[i]);
        g_xk[i] = __float2half_rn(xk[i]);
        g_xv[i] = __float2half_rn(xv[i]);
    }
}

// ---------------- GEMM: C[m,n] = sum_k A[m,k] * W[n,k] + bias[n] ----------------
// Block tile 64x64, 8 warps (4 M-subtiles x 2 N-subtiles of 32), K-chunks of 64.
constexpr int LDH = 72;  // half smem leading dim (multiple of 8)
constexpr int LDF = 68;  // float smem leading dim (multiple of 4)

template<bool SPLIT_HEADS>
__global__ void __launch_bounds__(256) gemm_bias(
    const __half* __restrict__ A, const __half* __restrict__ W,
    const float* __restrict__ bias, void* __restrict__ Cout)
{
    __shared__ __align__(256) unsigned char sraw[2 * 64 * LDH * 2]; // 18432 B
    __half* As = (__half*)sraw;
    __half* Bs = As + 64 * LDH;
    float*  Cs = (float*)sraw;   // reused after K loop (17408 B <= 18432)

    const int tid = threadIdx.x;
    const int row = tid >> 2, cg = tid & 3;       // 64 rows x 4 col-groups of 16
    const int m0 = blockIdx.y * 64, n0 = blockIdx.x * 64;
    const int w = tid >> 5, wm = w & 3, wn = w >> 2;

    wmma::fragment<wmma::accumulator, 16, 16, 16, float> c[2];
    wmma::fill_fragment(c[0], 0.0f);
    wmma::fill_fragment(c[1], 0.0f);

    const __half* Ag = A + (size_t)(m0 + row) * D_MODEL + cg * 16;
    const __half* Wg = W + (size_t)(n0 + row) * D_MODEL + cg * 16;

    for (int k0 = 0; k0 < D_MODEL; k0 += 64) {
        *(uint4*)&As[row * LDH + cg * 16]     = *(const uint4*)(Ag + k0);
        *(uint4*)&As[row * LDH + cg * 16 + 8] = *(const uint4*)(Ag + k0 + 8);
        *(uint4*)&Bs[row * LDH + cg * 16]     = *(const uint4*)(Wg + k0);
        *(uint4*)&Bs[row * LDH + cg * 16 + 8] = *(const uint4*)(Wg + k0 + 8);
        __syncthreads();
        #pragma unroll
        for (int kk = 0; kk < 4; kk++) {
            wmma::fragment<wmma::matrix_a, 16, 16, 16, __half, wmma::row_major> af;
            wmma::load_matrix_sync(af, As + wm * 16 * LDH + kk * 16, LDH);
            #pragma unroll
            for (int j = 0; j < 2; j++) {
                wmma::fragment<wmma::matrix_b, 16, 16, 16, __half, wmma::col_major> bf;
                wmma::load_matrix_sync(bf, Bs + (wn * 32 + j * 16) * LDH + kk * 16, LDH);
                wmma::mma_sync(c[j], af, bf, c[j]);
            }
        }
        __syncthreads();
    }

    #pragma unroll
    for (int j = 0; j < 2; j++)
        wmma::store_matrix_sync(Cs + wm * 16 * LDF + wn * 32 + j * 16, c[j], LDF,
                                wmma::mem_row_major);
    __syncthreads();

    #pragma unroll
    for (int i = 0; i < 16; i++) {
        int cc = cg * 16 + i;
        float v = Cs[row * LDF + cc] + bias[n0 + cc];
        int m = m0 + row, n = n0 + cc;
        if (SPLIT_HEADS) {
            int b = m >> 11, s = m & (SEQ - 1);
            int h = n >> 6,  d = n & (DH - 1);
            ((__half*)Cout)[(((size_t)(b * NH + h) * SEQ + s) << 6) + d] = __float2half_rn(v);
        } else {
            ((float*)Cout)[(size_t)m * D_MODEL + n] = v;
        }
    }
}

// ---------------- flash attention: per (b,h), 64-query tiles ----------------
#define ATTN_SMEM 72704

__global__ void __launch_bounds__(256) attn_kernel(const int* __restrict__ mask)
{
    extern __shared__ __align__(256) unsigned char dsm[];
    __half* Qs = (__half*)dsm;                 // 64 x LDH
    __half* Ks = Qs + 64 * LDH;
    __half* Vs = Ks + 64 * LDH;
    __half* Ps = Vs + 64 * LDH;
    float*  Ss = (float*)(dsm + 4 * 64 * LDH * 2);   // offset 36864
    float*  Os = Ss + 64 * LDF;                      // offset 54272
    float*  m_s  = Os + 64 * LDF;                    // offset 71680
    float*  l_s  = m_s + 64;
    float*  al_s = l_s + 64;
    int*    mk   = (int*)(al_s + 64);                // 64 ints -> total 72704

    const int tid = threadIdx.x;
    const int r = tid >> 2, cg = tid & 3, cbase = cg * 16;
    const int w = tid >> 5, wm = w & 3, wn = w >> 2;
    const int bh = blockIdx.y;
    const int b = bh >> 4, h = bh & 15;
    const int q0 = blockIdx.x * 64;

    // load Q tile (stays resident)
    {
        const __half* Qg = g_Q + ((size_t)bh * SEQ + q0) * DH + cbase;
        *(uint4*)&Qs[r * LDH + cbase]     = *(const uint4*)(Qg + (size_t)r * DH);
        *(uint4*)&Qs[r * LDH + cbase + 8] = *(const uint4*)(Qg + (size_t)r * DH + 8);
    }
    if (tid < 64) { m_s[tid] = -1e30f; l_s[tid] = 0.0f; }
    #pragma unroll
    for (int i = 0; i < 16; i++) Os[r * LDF + cbase + i] = 0.0f;
    __syncthreads();

    for (int kt = 0; kt < SEQ / 64; kt++) {
        const __half* Kg = g_K + ((size_t)bh * SEQ + kt * 64) * DH + cbase;
        const __half* Vg = g_V + ((size_t)bh * SEQ + kt * 64) * DH + cbase;
        *(uint4*)&Ks[r * LDH + cbase]     = *(const uint4*)(Kg + (size_t)r * DH);
        *(uint4*)&Ks[r * LDH + cbase + 8] = *(const uint4*)(Kg + (size_t)r * DH + 8);
        *(uint4*)&Vs[r * LDH + cbase]     = *(const uint4*)(Vg + (size_t)r * DH);
        *(uint4*)&Vs[r * LDH + cbase + 8] = *(const uint4*)(Vg + (size_t)r * DH + 8);
        if (tid < 64) mk[tid] = mask[b * SEQ + kt * 64 + tid];
        __syncthreads();

        // S = Q K^T  (K stored [k][d] == col-major (d,k))
        wmma::fragment<wmma::accumulator, 16, 16, 16, float> sc[2];
        wmma::fill_fragment(sc[0], 0.0f);
        wmma::fill_fragment(sc[1], 0.0f);
        #pragma unroll
        for (int kk = 0; kk < 4; kk++) {
            wmma::fragment<wmma::matrix_a, 16, 16, 16, __half, wmma::row_major> af;
            wmma::load_matrix_sync(af, Qs + wm * 16 * LDH + kk * 16, LDH);
            #pragma unroll
            for (int j = 0; j < 2; j++) {
                wmma::fragment<wmma::matrix_b, 16, 16, 16, __half, wmma::col_major> bf;
                wmma::load_matrix_sync(bf, Ks + (wn * 32 + j * 16) * LDH + kk * 16, LDH);
                wmma::mma_sync(sc[j], af, bf, sc[j]);
            }
        }
        #pragma unroll
        for (int j = 0; j < 2; j++)
            wmma::store_matrix_sync(Ss + wm * 16 * LDF + wn * 32 + j * 16, sc[j], LDF,
                                    wmma::mem_row_major);
        __syncthreads();

        // online softmax: 4 threads per row, 16 cols each
        float sv[16];
        float mx = -1e30f;
        #pragma unroll
        for (int i = 0; i < 16; i++) {
            int cc = cbase + i;
            float s = Ss[r * LDF + cc] * 0.125f;       // 1/sqrt(64)
            if (mk[cc] == 0) s = -1000000000.0f;        // NEG
            sv[i] = s;
            mx = fmaxf(mx, s);
        }
        mx = fmaxf(mx, __shfl_xor_sync(0xffffffffu, mx, 1));
        mx = fmaxf(mx, __shfl_xor_sync(0xffffffffu, mx, 2));
        float mold = m_s[r];
        float mnew = fmaxf(mold, mx);
        float sum = 0.0f;
        #pragma unroll
        for (int i = 0; i < 16; i++) {
            float p = __expf(sv[i] - mnew);
            sum += p;
            Ps[r * LDH + cbase + i] = __float2half_rn(p);
        }
        sum += __shfl_xor_sync(0xffffffffu, sum, 1);
        sum += __shfl_xor_sync(0xffffffffu, sum, 2);
        if (cg == 0) {
            float al = __expf(mold - mnew);
            al_s[r] = al;
            l_s[r]  = l_s[r] * al + sum;
            m_s[r]  = mnew;
        }
        __syncthreads();

        // rescale running output
        float ar = al_s[r];
        #pragma unroll
        for (int i = 0; i < 16; i++) Os[r * LDF + cbase + i] *= ar;
        __syncthreads();

        // O += P V  (V stored [k][d] row-major)
        #pragma unroll
        for (int j = 0; j < 2; j++) {
            wmma::fragment<wmma::accumulator, 16, 16, 16, float> oc;
            wmma::load_matrix_sync(oc, Os + wm * 16 * LDF + wn * 32 + j * 16, LDF,
                                   wmma::mem_row_major);
            #pragma unroll
            for (int kk = 0; kk < 4; kk++) {
                wmma::fragment<wmma::matrix_a, 16, 16, 16, __half, wmma::row_major> af;
                wmma::load_matrix_sync(af, Ps + wm * 16 * LDH + kk * 16, LDH);
                wmma::fragment<wmma::matrix_b, 16, 16, 16, __half, wmma::row_major> bf;
                wmma::load_matrix_sync(bf, Vs + kk * 16 * LDH + wn * 32 + j * 16, LDH);
                wmma::mma_sync(oc, af, bf, oc);
            }
            wmma::store_matrix_sync(Os + wm * 16 * LDF + wn * 32 + j * 16, oc, LDF,
                                    wmma::mem_row_major);
        }
        __syncthreads();
    }

    // finalize: ctx[b, s, h*64 + d] fp16
    float linv = 1.0f / l_s[r];
    #pragma unroll
    for (int i = 0; i < 16; i++) {
        int cc = cbase + i;
        g_ctx[((size_t)(b * SEQ + q0 + r)) * D_MODEL + h * DH + cc] =
            __float2half_rn(Os[r * LDF + cc] * linv);
    }
}

// ---------------- launch ----------------
extern "C" void kernel_launch(void* const* d_in, const int* in_sizes, int n_in,
                              void* d_out, int out_size)
{
    const float* xq   = (const float*)d_in[0];
    const float* xk   = (const float*)d_in[1];
    const float* xv   = (const float*)d_in[2];
    const int*   mask = (const int*)  d_in[3];
    const float* Wq   = (const float*)d_in[4];
    const float* bq   = (const float*)d_in[5];
    const float* Wk   = (const float*)d_in[6];
    const float* bk   = (const float*)d_in[7];
    const float* Wv   = (const float*)d_in[8];
    const float* bv   = (const float*)d_in[9];
    const float* Wo   = (const float*)d_in[10];
    const float* bo   = (const float*)d_in[11];

    void *p_xq, *p_xk, *p_xv, *p_Wq, *p_Wk, *p_Wv, *p_Wo, *p_Q, *p_K, *p_V, *p_ctx;
    cudaGetSymbolAddress(&p_xq, g_xq);
    cudaGetSymbolAddress(&p_xk, g_xk);
    cudaGetSymbolAddress(&p_xv, g_xv);
    cudaGetSymbolAddress(&p_Wq, g_Wq);
    cudaGetSymbolAddress(&p_Wk, g_Wk);
    cudaGetSymbolAddress(&p_Wv, g_Wv);
    cudaGetSymbolAddress(&p_Wo, g_Wo);
    cudaGetSymbolAddress(&p_Q,  g_Q);
    cudaGetSymbolAddress(&p_K,  g_K);
    cudaGetSymbolAddress(&p_V,  g_V);
    cudaGetSymbolAddress(&p_ctx, g_ctx);

    cvt_all<<<(M_TOT * D_MODEL + 255) / 256, 256>>>(xq, xk, xv, Wq, Wk, Wv, Wo);

    dim3 gg(D_MODEL / 64, M_TOT / 64);  // (16, 128)
    gemm_bias<true><<<gg, 256>>>((const __half*)p_xq, (const __half*)p_Wq, bq, p_Q);
    gemm_bias<true><<<gg, 256>>>((const __half*)p_xk, (const __half*)p_Wk, bk, p_K);
    gemm_bias<true><<<gg, 256>>>((const __half*)p_xv, (const __half*)p_Wv, bv, p_V);

    cudaFuncSetAttribute(attn_kernel, cudaFuncAttributeMaxDynamicSharedMemorySize, ATTN_SMEM);
    attn_kernel<<<dim3(SEQ / 64, BATCH * NH), 256, ATTN_SMEM>>>(mask);

    gemm_bias<false><<<gg, 256>>>((const __half*)p_ctx, (const __half*)p_Wo, bo, d_out);
}

// round 10
// speedup vs baseline: 2.2049x; 2.2049x over previous
#include <cuda_runtime.h>
#include <cuda_fp16.h>
#include <mma.h>
#include <stdint.h>

using namespace nvcuda;

#define D_MODEL 1024
#define NH      16
#define DH      64
#define BATCH   4
#define SEQ     2048
#define M_TOT   (BATCH * SEQ)   // 8192
#define NEG     -1000000000.0f

// ---------------- device scratch (no allocs allowed) ----------------
__device__ __half g_xq[(size_t)M_TOT * D_MODEL];
__device__ __half g_xk[(size_t)M_TOT * D_MODEL];
__device__ __half g_xv[(size_t)M_TOT * D_MODEL];
__device__ __half g_Wq[(size_t)D_MODEL * D_MODEL];
__device__ __half g_Wk[(size_t)D_MODEL * D_MODEL];
__device__ __half g_Wv[(size_t)D_MODEL * D_MODEL];
__device__ __half g_Wo[(size_t)D_MODEL * D_MODEL];
__device__ __half g_Q[(size_t)M_TOT * D_MODEL];   // [B*H][S][DH], pre-scaled by 0.125
__device__ __half g_K[(size_t)M_TOT * D_MODEL];   // [B*H][S][DH]
__device__ __half g_V[(size_t)M_TOT * D_MODEL];   // [B*H][DH][S]  (TRANSPOSED per head)
__device__ __half g_ctx[(size_t)M_TOT * D_MODEL]; // [B*S][H*DH]

// ---------------- small PTX helpers ----------------
__device__ __forceinline__ uint32_t smem_u32(const void* p) {
    return (uint32_t)__cvta_generic_to_shared(p);
}
__device__ __forceinline__ void cp16(uint32_t dst, const void* src) {
    asm volatile("cp.async.cg.shared.global [%0], [%1], 16;\n" :: "r"(dst), "l"(src));
}
__device__ __forceinline__ void cp4(uint32_t dst, const void* src) {
    asm volatile("cp.async.ca.shared.global [%0], [%1], 4;\n" :: "r"(dst), "l"(src));
}
__device__ __forceinline__ void cp_commit() {
    asm volatile("cp.async.commit_group;\n");
}
template<int N>
__device__ __forceinline__ void cp_wait() {
    asm volatile("cp.async.wait_group %0;\n" :: "n"(N));
}
__device__ __forceinline__ void ldm_x4(uint32_t& r0, uint32_t& r1, uint32_t& r2, uint32_t& r3,
                                       uint32_t addr) {
    asm volatile("ldmatrix.sync.aligned.m8n8.x4.shared.b16 {%0,%1,%2,%3}, [%4];\n"
                 : "=r"(r0), "=r"(r1), "=r"(r2), "=r"(r3) : "r"(addr));
}
__device__ __forceinline__ void mma16816(float c[4], uint32_t a0, uint32_t a1, uint32_t a2,
                                         uint32_t a3, uint32_t b0, uint32_t b1) {
    asm volatile(
        "mma.sync.aligned.m16n8k16.row.col.f32.f16.f16.f32 "
        "{%0,%1,%2,%3}, {%4,%5,%6,%7}, {%8,%9}, {%0,%1,%2,%3};\n"
        : "+f"(c[0]), "+f"(c[1]), "+f"(c[2]), "+f"(c[3])
        : "r"(a0), "r"(a1), "r"(a2), "r"(a3), "r"(b0), "r"(b1));
}
__device__ __forceinline__ uint32_t f2h2(float a, float b) {
    __half2 t = __floats2half2_rn(a, b);
    return *reinterpret_cast<uint32_t*>(&t);
}

// ---------------- fp32 -> fp16 conversion (x and W) ----------------
__global__ void __launch_bounds__(256) cvt_all(
    const float* __restrict__ xq, const float* __restrict__ xk, const float* __restrict__ xv,
    const float* __restrict__ wq, const float* __restrict__ wk,
    const float* __restrict__ wv, const float* __restrict__ wo)
{
    size_t i = (size_t)blockIdx.x * blockDim.x + threadIdx.x;
    if (i < (size_t)D_MODEL * D_MODEL) {
        g_Wq[i] = __float2half_rn(wq[i]);
        g_Wk[i] = __float2half_rn(wk[i]);
        g_Wv[i] = __float2half_rn(wv[i]);
        g_Wo[i] = __float2half_rn(wo[i]);
    }
    if (i < (size_t)M_TOT * D_MODEL) {
        g_xq[i] = __float2half_rn(xq[i]);
        g_xk[i] = __float2half_rn(xk[i]);
        g_xv[i] = __float2half_rn(xv[i]);
    }
}

// ---------------- GEMM v2: C[m,n] = sum_k A[m,k]*W[n,k] + bias[n] ----------------
// 128x128 block tile, BK=32, 8 warps (2m x 4n), warp tile 64x32, double-buffered cp.async.
// MODE 0: fp32 out [m][1024]        (final projection)
// MODE 1: fp16 out [bh][s][dh]*scale (Q with scale=0.125, K with 1.0)
// MODE 2: fp16 out [bh][dh][s]       (V transposed)
constexpr int GLD = 40;  // half smem leading dim (32 + 8 pad), 80B rows -> conflict-free LDSM
constexpr int CLD = 68;  // float staging leading dim

template<int MODE>
__global__ void __launch_bounds__(256) gemm2(
    const __half* __restrict__ A, const __half* __restrict__ W,
    const float* __restrict__ bias, void* __restrict__ out, float scale)
{
    __shared__ __align__(16) unsigned char sm[40960];
    __half* As0 = (__half*)sm;                   // [2][128][GLD]
    __half* Bs0 = (__half*)sm + 2 * 128 * GLD;   // [2][128][GLD]
    float*  Cs  = (float*)sm;                    // [128][CLD] = 34816B (epilogue reuse)

    const int tid = threadIdx.x;
    const int lane = tid & 31, wid = tid >> 5;
    const int wm = wid & 1, wn = wid >> 1;
    const int m0 = blockIdx.y * 128, n0 = blockIdx.x * 128;

    wmma::fragment<wmma::accumulator, 16, 16, 16, float> c[4][2];
    #pragma unroll
    for (int i = 0; i < 4; i++)
        #pragma unroll
        for (int j = 0; j < 2; j++)
            wmma::fill_fragment(c[i][j], 0.0f);

    auto loadAB = [&](int kt, int buf) {
        int k0 = kt * 32;
        __half* Asb = As0 + buf * 128 * GLD;
        __half* Bsb = Bs0 + buf * 128 * GLD;
        #pragma unroll
        for (int i = 0; i < 2; i++) {
            int cch = tid + i * 256;          // 0..511
            int row = cch >> 2, c8 = (cch & 3) * 8;
            cp16(smem_u32(Asb + row * GLD + c8), A + (size_t)(m0 + row) * D_MODEL + k0 + c8);
            cp16(smem_u32(Bsb + row * GLD + c8), W + (size_t)(n0 + row) * D_MODEL + k0 + c8);
        }
    };

    loadAB(0, 0); cp_commit();
    loadAB(1, 1); cp_commit();
    cp_wait<1>(); __syncthreads();

    for (int kt = 0; kt < D_MODEL / 32; kt++) {
        int buf = kt & 1;
        const __half* Asb = As0 + buf * 128 * GLD;
        const __half* Bsb = Bs0 + buf * 128 * GLD;
        #pragma unroll
        for (int kk = 0; kk < 2; kk++) {
            wmma::fragment<wmma::matrix_a, 16, 16, 16, __half, wmma::row_major> af[4];
            wmma::fragment<wmma::matrix_b, 16, 16, 16, __half, wmma::col_major> bf[2];
            #pragma unroll
            for (int i = 0; i < 4; i++)
                wmma::load_matrix_sync(af[i], Asb + (wm * 64 + i * 16) * GLD + kk * 16, GLD);
            #pragma unroll
            for (int j = 0; j < 2; j++)
                wmma::load_matrix_sync(bf[j], Bsb + (wn * 32 + j * 16) * GLD + kk * 16, GLD);
            #pragma unroll
            for (int i = 0; i < 4; i++)
                #pragma unroll
                for (int j = 0; j < 2; j++)
                    wmma::mma_sync(c[i][j], af[i], bf[j], c[i][j]);
        }
        __syncthreads();
        if (kt + 2 < D_MODEL / 32) { loadAB(kt + 2, buf); cp_commit(); cp_wait<1>(); }
        else                       { cp_wait<0>(); }
        __syncthreads();
    }

    // epilogue: two 64-column passes through smem staging
    const int b = m0 >> 11;          // 128 | 2048 so whole block is one batch
    const int sbase = m0 & (SEQ - 1);
    #pragma unroll
    for (int p = 0; p < 2; p++) {
        if ((wn >> 1) == p) {
            #pragma unroll
            for (int i = 0; i < 4; i++)
                #pragma unroll
                for (int j = 0; j < 2; j++)
                    wmma::store_matrix_sync(Cs + (wm * 64 + i * 16) * CLD + (wn & 1) * 32 + j * 16,
                                            c[i][j], CLD, wmma::mem_row_major);
        }
        __syncthreads();

        if (MODE == 2) {
            // V: write transposed [bh][d][s]; thread owns one column, 32 consecutive s
            int col = tid & 63;
            int rbase = (tid >> 6) * 32;
            int n = n0 + p * 64 + col;
            int h = n >> 6, d = n & (DH - 1);
            float bv = bias[n];
            __half* dst = (__half*)out + (((size_t)(b * NH + h) * DH + d) * SEQ) + sbase + rbase;
            #pragma unroll
            for (int r = 0; r < 32; r += 2) {
                float v0 = Cs[(rbase + r) * CLD + col] + bv;
                float v1 = Cs[(rbase + r + 1) * CLD + col] + bv;
                *(__half2*)(dst + r) = __floats2half2_rn(v0, v1);
            }
        } else {
            int row = tid >> 1;
            int colseg = (tid & 1) * 32;
            int nbase = n0 + p * 64 + colseg;
            int m = m0 + row;
            if (MODE == 0) {
                float* dst = (float*)out + (size_t)m * D_MODEL + nbase;
                #pragma unroll
                for (int i = 0; i < 32; i += 4) {
                    float4 v;
                    v.x = Cs[row * CLD + colseg + i]     + bias[nbase + i];
                    v.y = Cs[row * CLD + colseg + i + 1] + bias[nbase + i + 1];
                    v.z = Cs[row * CLD + colseg + i + 2] + bias[nbase + i + 2];
                    v.w = Cs[row * CLD + colseg + i + 3] + bias[nbase + i + 3];
                    *(float4*)(dst + i) = v;
                }
            } else {  // MODE 1: [bh][s][dh], scaled
                int h = nbase >> 6, d0 = nbase & (DH - 1);  // 32-col span stays in one head
                int s = m & (SEQ - 1), bb = m >> 11;
                __half* dst = (__half*)out +
                    (((size_t)(bb * NH + h) * SEQ + s) * DH) + d0;
                #pragma unroll
                for (int i = 0; i < 32; i += 2) {
                    float v0 = (Cs[row * CLD + colseg + i]     + bias[nbase + i])     * scale;
                    float v1 = (Cs[row * CLD + colseg + i + 1] + bias[nbase + i + 1]) * scale;
                    *(__half2*)(dst + i) = __floats2half2_rn(v0, v1);
                }
            }
        }
        __syncthreads();
    }
}

// ---------------- flash attention v2: register-resident, raw mma ----------------
// Block: 128 threads (4 warps), 64 queries (16 per warp). Key chunks of 64,
// K/V/mask double-buffered via cp.async. Q/S/P/O all in registers.
constexpr int ALD = 72;  // 144B rows -> conflict-free ldmatrix

__global__ void __launch_bounds__(128) attn2(const int* __restrict__ mask)
{
    __shared__ __align__(16) __half Qs[64][ALD];
    __shared__ __align__(16) __half Ks[2][64][ALD];
    __shared__ __align__(16) __half Vs[2][64][ALD];   // V^T chunk: rows=d, cols=s
    __shared__ int mks[2][64];

    const int tid = threadIdx.x;
    const int lane = tid & 31, wid = tid >> 5;
    const int bh = blockIdx.y, b = bh >> 4, h = bh & (NH - 1);
    const int q0 = blockIdx.x * 64;

    const __half* Kbase = g_K + (size_t)bh * SEQ * DH;
    const __half* Vbase = g_V + (size_t)bh * DH * SEQ;
    const int* mbase = mask + b * SEQ;

    // FIX (R7 NaN): 64 rows x 64 halves = 512 16B chunks -> row = cch>>3,
    // c8 = (cch&7)*8, 4 iterations of 128 threads. Previous code used
    // row = cch>>2 / 2 iterations, leaving halves [32..63] of every row
    // uninitialized.
    auto loadKV = [&](int kt, int buf) {
        int s0 = kt * 64;
        #pragma unroll
        for (int i = 0; i < 4; i++) {
            int cch = tid + i * 128;              // 0..511
            int row = cch >> 3, c8 = (cch & 7) * 8;
            cp16(smem_u32(&Ks[buf][row][c8]), Kbase + (size_t)(s0 + row) * DH + c8);
            cp16(smem_u32(&Vs[buf][row][c8]), Vbase + (size_t)row * SEQ + s0 + c8);
        }
        if (tid < 64) cp4(smem_u32(&mks[buf][tid]), mbase + s0 + tid);
    };

    // prologue: Q + chunk0 in group 0, chunk1 in group 1
    {
        #pragma unroll
        for (int i = 0; i < 4; i++) {
            int cch = tid + i * 128;              // 0..511
            int row = cch >> 3, c8 = (cch & 7) * 8;
            cp16(smem_u32(&Qs[row][c8]), g_Q + ((size_t)bh * SEQ + q0 + row) * DH + c8);
        }
        loadKV(0, 0); cp_commit();
        loadKV(1, 1); cp_commit();
        cp_wait<1>(); __syncthreads();
    }

    // Q fragments: 4 k-slices of 16
    uint32_t qf[4][4];
    {
        int roff = (lane & 7) + (lane & 8);
        int coff = (lane & 16) >> 1;
        #pragma unroll
        for (int kf = 0; kf < 4; kf++)
            ldm_x4(qf[kf][0], qf[kf][1], qf[kf][2], qf[kf][3],
                   smem_u32(&Qs[wid * 16 + roff][kf * 16 + coff]));
    }

    float oacc[8][4];
    #pragma unroll
    for (int nt = 0; nt < 8; nt++)
        #pragma unroll
        for (int j = 0; j < 4; j++) oacc[nt][j] = 0.0f;
    float mrun_lo = -1e30f, mrun_hi = -1e30f, lrun_lo = 0.0f, lrun_hi = 0.0f;

    const int broff = (lane & 7) | ((lane & 16) >> 1);  // row-within-16 for B ldmatrix
    const int bcoff = lane & 8;                          // k-half select

    for (int kt = 0; kt < SEQ / 64; kt++) {
        int buf = kt & 1;

        // ---- S = Q K^T (16x64 per warp), Q already scaled by 1/sqrt(DH) ----
        float sacc[8][4];
        #pragma unroll
        for (int nt = 0; nt < 8; nt++)
            #pragma unroll
            for (int j = 0; j < 4; j++) sacc[nt][j] = 0.0f;
        #pragma unroll
        for (int kf = 0; kf < 4; kf++) {
            #pragma unroll
            for (int ntp = 0; ntp < 4; ntp++) {
                uint32_t b0, b1, b2, b3;
                ldm_x4(b0, b1, b2, b3,
                       smem_u32(&Ks[buf][ntp * 16 + broff][kf * 16 + bcoff]));
                mma16816(sacc[2 * ntp],     qf[kf][0], qf[kf][1], qf[kf][2], qf[kf][3], b0, b1);
                mma16816(sacc[2 * ntp + 1], qf[kf][0], qf[kf][1], qf[kf][2], qf[kf][3], b2, b3);
            }
        }

        // ---- mask + online softmax (register-resident) ----
        float mlo = -1e30f, mhi = -1e30f;
        #pragma unroll
        for (int nt = 0; nt < 8; nt++) {
            int mi = nt * 8 + (lane & 3) * 2;
            bool k0 = mks[buf][mi] != 0, k1 = mks[buf][mi + 1] != 0;
            sacc[nt][0] = k0 ? sacc[nt][0] : NEG;
            sacc[nt][1] = k1 ? sacc[nt][1] : NEG;
            sacc[nt][2] = k0 ? sacc[nt][2] : NEG;
            sacc[nt][3] = k1 ? sacc[nt][3] : NEG;
            mlo = fmaxf(mlo, fmaxf(sacc[nt][0], sacc[nt][1]));
            mhi = fmaxf(mhi, fmaxf(sacc[nt][2], sacc[nt][3]));
        }
        mlo = fmaxf(mlo, __shfl_xor_sync(0xffffffffu, mlo, 1));
        mlo = fmaxf(mlo, __shfl_xor_sync(0xffffffffu, mlo, 2));
        mhi = fmaxf(mhi, __shfl_xor_sync(0xffffffffu, mhi, 1));
        mhi = fmaxf(mhi, __shfl_xor_sync(0xffffffffu, mhi, 2));

        float mnl = fmaxf(mrun_lo, mlo), mnh = fmaxf(mrun_hi, mhi);
        float alo = __expf(mrun_lo - mnl), ahi = __expf(mrun_hi - mnh);
        mrun_lo = mnl; mrun_hi = mnh;

        float slo = 0.0f, shi = 0.0f;
        #pragma unroll
        for (int nt = 0; nt < 8; nt++) {
            sacc[nt][0] = __expf(sacc[nt][0] - mnl); slo += sacc[nt][0];
            sacc[nt][1] = __expf(sacc[nt][1] - mnl); slo += sacc[nt][1];
            sacc[nt][2] = __expf(sacc[nt][2] - mnh); shi += sacc[nt][2];
            sacc[nt][3] = __expf(sacc[nt][3] - mnh); shi += sacc[nt][3];
        }
        slo += __shfl_xor_sync(0xffffffffu, slo, 1);
        slo += __shfl_xor_sync(0xffffffffu, slo, 2);
        shi += __shfl_xor_sync(0xffffffffu, shi, 1);
        shi += __shfl_xor_sync(0xffffffffu, shi, 2);
        lrun_lo = lrun_lo * alo + slo;
        lrun_hi = lrun_hi * ahi + shi;

        #pragma unroll
        for (int nt = 0; nt < 8; nt++) {
            oacc[nt][0] *= alo; oacc[nt][1] *= alo;
            oacc[nt][2] *= ahi; oacc[nt][3] *= ahi;
        }

        // ---- repack P (S-accum layout == A-frag layout) ----
        uint32_t pf[4][4];
        #pragma unroll
        for (int kf = 0; kf < 4; kf++) {
            pf[kf][0] = f2h2(sacc[2 * kf][0],     sacc[2 * kf][1]);
            pf[kf][1] = f2h2(sacc[2 * kf][2],     sacc[2 * kf][3]);
            pf[kf][2] = f2h2(sacc[2 * kf + 1][0], sacc[2 * kf + 1][1]);
            pf[kf][3] = f2h2(sacc[2 * kf + 1][2], sacc[2 * kf + 1][3]);
        }

        // ---- O += P V (V^T in smem: rows=d, cols=s) ----
        #pragma unroll
        for (int kf = 0; kf < 4; kf++) {
            #pragma unroll
            for (int ntp = 0; ntp < 4; ntp++) {
                uint32_t b0, b1, b2, b3;
                ldm_x4(b0, b1, b2, b3,
                       smem_u32(&Vs[buf][ntp * 16 + broff][kf * 16 + bcoff]));
                mma16816(oacc[2 * ntp],     pf[kf][0], pf[kf][1], pf[kf][2], pf[kf][3], b0, b1);
                mma16816(oacc[2 * ntp + 1], pf[kf][0], pf[kf][1], pf[kf][2], pf[kf][3], b2, b3);
            }
        }

        __syncthreads();
        if (kt + 2 < SEQ / 64) { loadKV(kt + 2, buf); cp_commit(); cp_wait<1>(); }
        else                   { cp_wait<0>(); }
        __syncthreads();
    }

    // ---- finalize: ctx[b*S + q][h*64 + d], fp16 ----
    float ilo = 1.0f / lrun_lo, ihi = 1.0f / lrun_hi;
    int rlo = q0 + wid * 16 + (lane >> 2);
    __half* outlo = g_ctx + ((size_t)(b * SEQ) + rlo) * D_MODEL + h * DH;
    __half* outhi = outlo + (size_t)8 * D_MODEL;
    #pragma unroll
    for (int nt = 0; nt < 8; nt++) {
        int d0 = nt * 8 + (lane & 3) * 2;
        *(__half2*)(outlo + d0) = __floats2half2_rn(oacc[nt][0] * ilo, oacc[nt][1] * ilo);
        *(__half2*)(outhi + d0) = __floats2half2_rn(oacc[nt][2] * ihi, oacc[nt][3] * ihi);
    }
}

// ---------------- launch ----------------
extern "C" void kernel_launch(void* const* d_in, const int* in_sizes, int n_in,
                              void* d_out, int out_size)
{
    const float* xq   = (const float*)d_in[0];
    const float* xk   = (const float*)d_in[1];
    const float* xv   = (const float*)d_in[2];
    const int*   mask = (const int*)  d_in[3];
    const float* Wq   = (const float*)d_in[4];
    const float* bq   = (const float*)d_in[5];
    const float* Wk   = (const float*)d_in[6];
    const float* bk   = (const float*)d_in[7];
    const float* Wv   = (const float*)d_in[8];
    const float* bv   = (const float*)d_in[9];
    const float* Wo   = (const float*)d_in[10];
    const float* bo   = (const float*)d_in[11];

    void *p_xq, *p_xk, *p_xv, *p_Wq, *p_Wk, *p_Wv, *p_Wo, *p_Q, *p_K, *p_V, *p_ctx;
    cudaGetSymbolAddress(&p_xq, g_xq);
    cudaGetSymbolAddress(&p_xk, g_xk);
    cudaGetSymbolAddress(&p_xv, g_xv);
    cudaGetSymbolAddress(&p_Wq, g_Wq);
    cudaGetSymbolAddress(&p_Wk, g_Wk);
    cudaGetSymbolAddress(&p_Wv, g_Wv);
    cudaGetSymbolAddress(&p_Wo, g_Wo);
    cudaGetSymbolAddress(&p_Q,  g_Q);
    cudaGetSymbolAddress(&p_K,  g_K);
    cudaGetSymbolAddress(&p_V,  g_V);
    cudaGetSymbolAddress(&p_ctx, g_ctx);

    cvt_all<<<(M_TOT * D_MODEL + 255) / 256, 256>>>(xq, xk, xv, Wq, Wk, Wv, Wo);

    dim3 gg(D_MODEL / 128, M_TOT / 128);  // (8, 64)
    gemm2<1><<<gg, 256>>>((const __half*)p_xq, (const __half*)p_Wq, bq, p_Q, 0.125f);
    gemm2<1><<<gg, 256>>>((const __half*)p_xk, (const __half*)p_Wk, bk, p_K, 1.0f);
    gemm2<2><<<gg, 256>>>((const __half*)p_xv, (const __half*)p_Wv, bv, p_V, 1.0f);

    attn2<<<dim3(SEQ / 64, BATCH * NH), 128>>>(mask);

    gemm2<0><<<gg, 256>>>((const __half*)p_ctx, (const __half*)p_Wo, bo, d_out, 1.0f);
}

// round 12
// speedup vs baseline: 2.3159x; 1.0503x over previous
#include <cuda_runtime.h>
#include <cuda_fp16.h>
#include <mma.h>
#include <stdint.h>

using namespace nvcuda;

#define D_MODEL 1024
#define NH      16
#define DH      64
#define BATCH   4
#define SEQ     2048
#define M_TOT   (BATCH * SEQ)   // 8192
#define NEG     -1000000000.0f

// ---------------- device scratch (no allocs allowed) ----------------
__device__ __half g_xq[(size_t)M_TOT * D_MODEL];
__device__ __half g_xk[(size_t)M_TOT * D_MODEL];
__device__ __half g_xv[(size_t)M_TOT * D_MODEL];
__device__ __half g_Wq[(size_t)D_MODEL * D_MODEL];
__device__ __half g_Wk[(size_t)D_MODEL * D_MODEL];
__device__ __half g_Wv[(size_t)D_MODEL * D_MODEL];
__device__ __half g_Wo[(size_t)D_MODEL * D_MODEL];
__device__ __half g_Q[(size_t)M_TOT * D_MODEL];   // [B*H][S][DH], pre-scaled by 0.125
__device__ __half g_K[(size_t)M_TOT * D_MODEL];   // [B*H][S][DH]
__device__ __half g_V[(size_t)M_TOT * D_MODEL];   // [B*H][DH][S]  (TRANSPOSED per head)
__device__ __half g_ctx[(size_t)M_TOT * D_MODEL]; // [B*S][H*DH]

// ---------------- small PTX helpers ----------------
__device__ __forceinline__ uint32_t smem_u32(const void* p) {
    return (uint32_t)__cvta_generic_to_shared(p);
}
__device__ __forceinline__ void cp16(uint32_t dst, const void* src) {
    asm volatile("cp.async.cg.shared.global [%0], [%1], 16;\n" :: "r"(dst), "l"(src));
}
__device__ __forceinline__ void cp4(uint32_t dst, const void* src) {
    asm volatile("cp.async.ca.shared.global [%0], [%1], 4;\n" :: "r"(dst), "l"(src));
}
__device__ __forceinline__ void cp_commit() {
    asm volatile("cp.async.commit_group;\n");
}
template<int N>
__device__ __forceinline__ void cp_wait() {
    asm volatile("cp.async.wait_group %0;\n" :: "n"(N));
}
__device__ __forceinline__ void ldm_x4(uint32_t& r0, uint32_t& r1, uint32_t& r2, uint32_t& r3,
                                       uint32_t addr) {
    asm volatile("ldmatrix.sync.aligned.m8n8.x4.shared.b16 {%0,%1,%2,%3}, [%4];\n"
                 : "=r"(r0), "=r"(r1), "=r"(r2), "=r"(r3) : "r"(addr));
}
__device__ __forceinline__ void mma16816(float c[4], uint32_t a0, uint32_t a1, uint32_t a2,
                                         uint32_t a3, uint32_t b0, uint32_t b1) {
    asm volatile(
        "mma.sync.aligned.m16n8k16.row.col.f32.f16.f16.f32 "
        "{%0,%1,%2,%3}, {%4,%5,%6,%7}, {%8,%9}, {%0,%1,%2,%3};\n"
        : "+f"(c[0]), "+f"(c[1]), "+f"(c[2]), "+f"(c[3])
        : "r"(a0), "r"(a1), "r"(a2), "r"(a3), "r"(b0), "r"(b1));
}
__device__ __forceinline__ uint32_t f2h2(float a, float b) {
    __half2 t = __floats2half2_rn(a, b);
    return *reinterpret_cast<uint32_t*>(&t);
}

// ---------------- fp32 -> fp16 conversion (x and W) ----------------
__global__ void __launch_bounds__(256) cvt_all(
    const float* __restrict__ xq, const float* __restrict__ xk, const float* __restrict__ xv,
    const float* __restrict__ wq, const float* __restrict__ wk,
    const float* __restrict__ wv, const float* __restrict__ wo)
{
    size_t i = (size_t)blockIdx.x * blockDim.x + threadIdx.x;
    if (i < (size_t)D_MODEL * D_MODEL) {
        g_Wq[i] = __float2half_rn(wq[i]);
        g_Wk[i] = __float2half_rn(wk[i]);
        g_Wv[i] = __float2half_rn(wv[i]);
        g_Wo[i] = __float2half_rn(wo[i]);
    }
    if (i < (size_t)M_TOT * D_MODEL) {
        g_xq[i] = __float2half_rn(xq[i]);
        g_xk[i] = __float2half_rn(xk[i]);
        g_xv[i] = __float2half_rn(xv[i]);
    }
}

// ---------------- GEMM v3: C[m,n] = sum_k A[m,k]*W[n,k] + bias[n] ----------------
// 128x128 block tile, BK=32, 8 warps (2m x 4n), warp tile 64x32.
// 4-stage cp.async pipeline, ONE __syncthreads per K-iteration.
// MODE 0: fp32 out [m][1024]        (final projection)
// MODE 1: fp16 out [bh][s][dh]*scale (Q with scale=0.125, K with 1.0)
// MODE 2: fp16 out [bh][dh][s]       (V transposed)
constexpr int GLD = 40;   // half smem leading dim (32 + 8 pad)
constexpr int CLD = 68;   // float staging leading dim
constexpr int GSTAGE_B = 128 * GLD;            // halves per stage per tensor
#define GEMM_SMEM (4 * GSTAGE_B * 2 * 2)       // 81920 bytes

template<int MODE>
__global__ void __launch_bounds__(256) gemm2(
    const __half* __restrict__ A, const __half* __restrict__ W,
    const float* __restrict__ bias, void* __restrict__ out, float scale)
{
    extern __shared__ __align__(16) unsigned char gsm[];
    __half* As0 = (__half*)gsm;                  // [4][128][GLD]
    __half* Bs0 = As0 + 4 * GSTAGE_B;            // [4][128][GLD]
    float*  Cs  = (float*)gsm;                   // [128][CLD] = 34816B (epilogue reuse)

    const int tid = threadIdx.x;
    const int wid = tid >> 5;
    const int wm = wid & 1, wn = wid >> 1;
    const int m0 = blockIdx.y * 128, n0 = blockIdx.x * 128;

    wmma::fragment<wmma::accumulator, 16, 16, 16, float> c[4][2];
    #pragma unroll
    for (int i = 0; i < 4; i++)
        #pragma unroll
        for (int j = 0; j < 2; j++)
            wmma::fill_fragment(c[i][j], 0.0f);

    auto loadAB = [&](int kt, int buf) {
        int k0 = kt * 32;
        __half* Asb = As0 + buf * GSTAGE_B;
        __half* Bsb = Bs0 + buf * GSTAGE_B;
        #pragma unroll
        for (int i = 0; i < 2; i++) {
            int cch = tid + i * 256;          // 0..511
            int row = cch >> 2, c8 = (cch & 3) * 8;
            cp16(smem_u32(Asb + row * GLD + c8), A + (size_t)(m0 + row) * D_MODEL + k0 + c8);
            cp16(smem_u32(Bsb + row * GLD + c8), W + (size_t)(n0 + row) * D_MODEL + k0 + c8);
        }
    };

    const int KT = D_MODEL / 32;  // 32
    loadAB(0, 0); cp_commit();
    loadAB(1, 1); cp_commit();
    loadAB(2, 2); cp_commit();

    for (int kt = 0; kt < KT; kt++) {
        cp_wait<2>(); __syncthreads();
        const int buf = kt & 3;
        const __half* Asb = As0 + buf * GSTAGE_B;
        const __half* Bsb = Bs0 + buf * GSTAGE_B;
        #pragma unroll
        for (int kk = 0; kk < 2; kk++) {
            wmma::fragment<wmma::matrix_a, 16, 16, 16, __half, wmma::row_major> af[4];
            wmma::fragment<wmma::matrix_b, 16, 16, 16, __half, wmma::col_major> bf[2];
            #pragma unroll
            for (int i = 0; i < 4; i++)
                wmma::load_matrix_sync(af[i], Asb + (wm * 64 + i * 16) * GLD + kk * 16, GLD);
            #pragma unroll
            for (int j = 0; j < 2; j++)
                wmma::load_matrix_sync(bf[j], Bsb + (wn * 32 + j * 16) * GLD + kk * 16, GLD);
            #pragma unroll
            for (int i = 0; i < 4; i++)
                #pragma unroll
                for (int j = 0; j < 2; j++)
                    wmma::mma_sync(c[i][j], af[i], bf[j], c[i][j]);
        }
        // stage kt+3 overwrites buffer (kt-1)&3: all warps passed this iter's
        // barrier, so iter kt-1 reads are complete. Always commit (empty group
        // when exhausted) to keep wait<2> accounting uniform.
        if (kt + 3 < KT) loadAB(kt + 3, (kt + 3) & 3);
        cp_commit();
    }
    __syncthreads();   // protect Cs reuse (overlaps stage buffers)

    // epilogue: two 64-column passes through smem staging
    const int b = m0 >> 11;          // 128 | 2048 so whole block is one batch
    const int sbase = m0 & (SEQ - 1);
    #pragma unroll
    for (int p = 0; p < 2; p++) {
        if ((wn >> 1) == p) {
            #pragma unroll
            for (int i = 0; i < 4; i++)
                #pragma unroll
                for (int j = 0; j < 2; j++)
                    wmma::store_matrix_sync(Cs + (wm * 64 + i * 16) * CLD + (wn & 1) * 32 + j * 16,
                                            c[i][j], CLD, wmma::mem_row_major);
        }
        __syncthreads();

        if (MODE == 2) {
            // V: write transposed [bh][d][s]; thread owns one column, 32 consecutive s
            int col = tid & 63;
            int rbase = (tid >> 6) * 32;
            int n = n0 + p * 64 + col;
            int h = n >> 6, d = n & (DH - 1);
            float bv = bias[n];
            __half* dst = (__half*)out + (((size_t)(b * NH + h) * DH + d) * SEQ) + sbase + rbase;
            #pragma unroll
            for (int r = 0; r < 32; r += 2) {
                float v0 = Cs[(rbase + r) * CLD + col] + bv;
                float v1 = Cs[(rbase + r + 1) * CLD + col] + bv;
                *(__half2*)(dst + r) = __floats2half2_rn(v0, v1);
            }
        } else {
            int row = tid >> 1;
            int colseg = (tid & 1) * 32;
            int nbase = n0 + p * 64 + colseg;
            int m = m0 + row;
            if (MODE == 0) {
                float* dst = (float*)out + (size_t)m * D_MODEL + nbase;
                #pragma unroll
                for (int i = 0; i < 32; i += 4) {
                    float4 v;
                    v.x = Cs[row * CLD + colseg + i]     + bias[nbase + i];
                    v.y = Cs[row * CLD + colseg + i + 1] + bias[nbase + i + 1];
                    v.z = Cs[row * CLD + colseg + i + 2] + bias[nbase + i + 2];
                    v.w = Cs[row * CLD + colseg + i + 3] + bias[nbase + i + 3];
                    *(float4*)(dst + i) = v;
                }
            } else {  // MODE 1: [bh][s][dh], scaled
                int h = nbase >> 6, d0 = nbase & (DH - 1);  // 32-col span stays in one head
                int s = m & (SEQ - 1), bb = m >> 11;
                __half* dst = (__half*)out +
                    (((size_t)(bb * NH + h) * SEQ + s) * DH) + d0;
                #pragma unroll
                for (int i = 0; i < 32; i += 2) {
                    float v0 = (Cs[row * CLD + colseg + i]     + bias[nbase + i])     * scale;
                    float v1 = (Cs[row * CLD + colseg + i + 1] + bias[nbase + i + 1]) * scale;
                    *(__half2*)(dst + i) = __floats2half2_rn(v0, v1);
                }
            }
        }
        __syncthreads();
    }
}

// ---------------- flash attention v3: 128-query tiles, 8 warps ----------------
// Block: 256 threads (8 warps), 128 queries (16 per warp). Key chunks of 64,
// K/V/mask double-buffered via cp.async. Q/S/P/O all in registers.
// Halving CTA count halves K/V L2 traffic vs the 64-query version.
constexpr int ALD = 72;  // 144B rows -> conflict-free ldmatrix
#define ATTN_SMEM (128 * ALD * 2 + 2 * 64 * ALD * 2 * 2 + 2 * 64 * 4)   // 55808 B

__global__ void __launch_bounds__(256) attn2(const int* __restrict__ mask)
{
    extern __shared__ __align__(16) unsigned char asmem[];
    __half* Qs = (__half*)asmem;                 // [128][ALD]
    __half* Ks = Qs + 128 * ALD;                 // [2][64][ALD]
    __half* Vs = Ks + 2 * 64 * ALD;              // [2][64][ALD]  V^T: rows=d, cols=s
    int*    mks = (int*)(Vs + 2 * 64 * ALD);     // [2][64]

    const int tid = threadIdx.x;
    const int lane = tid & 31, wid = tid >> 5;
    const int bh = blockIdx.y, b = bh >> 4, h = bh & (NH - 1);
    const int q0 = blockIdx.x * 128;

    const __half* Kbase = g_K + (size_t)bh * SEQ * DH;
    const __half* Vbase = g_V + (size_t)bh * DH * SEQ;
    const int* mbase = mask + b * SEQ;

    auto loadKV = [&](int kt, int buf) {
        int s0 = kt * 64;
        #pragma unroll
        for (int i = 0; i < 2; i++) {
            int cch = tid + i * 256;              // 0..511 (64 rows x 8 chunks)
            int row = cch >> 3, c8 = (cch & 7) * 8;
            cp16(smem_u32(Ks + buf * 64 * ALD + row * ALD + c8),
                 Kbase + (size_t)(s0 + row) * DH + c8);
            cp16(smem_u32(Vs + buf * 64 * ALD + row * ALD + c8),
                 Vbase + (size_t)row * SEQ + s0 + c8);
        }
        if (tid < 64) cp4(smem_u32(mks + buf * 64 + tid), mbase + s0 + tid);
    };

    // prologue: Q + chunk0 in group 0, chunk1 in group 1
    {
        #pragma unroll
        for (int i = 0; i < 4; i++) {
            int cch = tid + i * 256;              // 0..1023 (128 rows x 8 chunks)
            int row = cch >> 3, c8 = (cch & 7) * 8;
            cp16(smem_u32(Qs + row * ALD + c8),
                 g_Q + ((size_t)bh * SEQ + q0 + row) * DH + c8);
        }
        loadKV(0, 0); cp_commit();
        loadKV(1, 1); cp_commit();
        cp_wait<1>(); __syncthreads();
    }

    // Q fragments: 4 k-slices of 16
    uint32_t qf[4][4];
    {
        int roff = (lane & 7) + (lane & 8);
        int coff = (lane & 16) >> 1;
        #pragma unroll
        for (int kf = 0; kf < 4; kf++)
            ldm_x4(qf[kf][0], qf[kf][1], qf[kf][2], qf[kf][3],
                   smem_u32(Qs + (wid * 16 + roff) * ALD + kf * 16 + coff));
    }

    float oacc[8][4];
    #pragma unroll
    for (int nt = 0; nt < 8; nt++)
        #pragma unroll
        for (int j = 0; j < 4; j++) oacc[nt][j] = 0.0f;
    float mrun_lo = -1e30f, mrun_hi = -1e30f, lrun_lo = 0.0f, lrun_hi = 0.0f;

    const int broff = (lane & 7) | ((lane & 16) >> 1);  // row-within-16 for B ldmatrix
    const int bcoff = lane & 8;                          // k-half select

    for (int kt = 0; kt < SEQ / 64; kt++) {
        int buf = kt & 1;
        const __half* Ksb = Ks + buf * 64 * ALD;
        const __half* Vsb = Vs + buf * 64 * ALD;
        const int*    mkb = mks + buf * 64;

        // ---- S = Q K^T (16x64 per warp), Q already scaled by 1/sqrt(DH) ----
        float sacc[8][4];
        #pragma unroll
        for (int nt = 0; nt < 8; nt++)
            #pragma unroll
            for (int j = 0; j < 4; j++) sacc[nt][j] = 0.0f;
        #pragma unroll
        for (int kf = 0; kf < 4; kf++) {
            #pragma unroll
            for (int ntp = 0; ntp < 4; ntp++) {
                uint32_t b0, b1, b2, b3;
                ldm_x4(b0, b1, b2, b3,
                       smem_u32(Ksb + (ntp * 16 + broff) * ALD + kf * 16 + bcoff));
                mma16816(sacc[2 * ntp],     qf[kf][0], qf[kf][1], qf[kf][2], qf[kf][3], b0, b1);
                mma16816(sacc[2 * ntp + 1], qf[kf][0], qf[kf][1], qf[kf][2], qf[kf][3], b2, b3);
            }
        }

        // ---- mask + online softmax (register-resident) ----
        float mlo = -1e30f, mhi = -1e30f;
        #pragma unroll
        for (int nt = 0; nt < 8; nt++) {
            int mi = nt * 8 + (lane & 3) * 2;
            bool k0 = mkb[mi] != 0, k1 = mkb[mi + 1] != 0;
            sacc[nt][0] = k0 ? sacc[nt][0] : NEG;
            sacc[nt][1] = k1 ? sacc[nt][1] : NEG;
            sacc[nt][2] = k0 ? sacc[nt][2] : NEG;
            sacc[nt][3] = k1 ? sacc[nt][3] : NEG;
            mlo = fmaxf(mlo, fmaxf(sacc[nt][0], sacc[nt][1]));
            mhi = fmaxf(mhi, fmaxf(sacc[nt][2], sacc[nt][3]));
        }
        mlo = fmaxf(mlo, __shfl_xor_sync(0xffffffffu, mlo, 1));
        mlo = fmaxf(mlo, __shfl_xor_sync(0xffffffffu, mlo, 2));
        mhi = fmaxf(mhi, __shfl_xor_sync(0xffffffffu, mhi, 1));
        mhi = fmaxf(mhi, __shfl_xor_sync(0xffffffffu, mhi, 2));

        float mnl = fmaxf(mrun_lo, mlo), mnh = fmaxf(mrun_hi, mhi);
        float alo = __expf(mrun_lo - mnl), ahi = __expf(mrun_hi - mnh);
        mrun_lo = mnl; mrun_hi = mnh;

        float slo = 0.0f, shi = 0.0f;
        #pragma unroll
        for (int nt = 0; nt < 8; nt++) {
            sacc[nt][0] = __expf(sacc[nt][0] - mnl); slo += sacc[nt][0];
            sacc[nt][1] = __expf(sacc[nt][1] - mnl); slo += sacc[nt][1];
            sacc[nt][2] = __expf(sacc[nt][2] - mnh); shi += sacc[nt][2];
            sacc[nt][3] = __expf(sacc[nt][3] - mnh); shi += sacc[nt][3];
        }
        slo += __shfl_xor_sync(0xffffffffu, slo, 1);
        slo += __shfl_xor_sync(0xffffffffu, slo, 2);
        shi += __shfl_xor_sync(0xffffffffu, shi, 1);
        shi += __shfl_xor_sync(0xffffffffu, shi, 2);
        lrun_lo = lrun_lo * alo + slo;
        lrun_hi = lrun_hi * ahi + shi;

        #pragma unroll
        for (int nt = 0; nt < 8; nt++) {
            oacc[nt][0] *= alo; oacc[nt][1] *= alo;
            oacc[nt][2] *= ahi; oacc[nt][3] *= ahi;
        }

        // ---- repack P (S-accum layout == A-frag layout) ----
        uint32_t pf[4][4];
        #pragma unroll
        for (int kf = 0; kf < 4; kf++) {
            pf[kf][0] = f2h2(sacc[2 * kf][0],     sacc[2 * kf][1]);
            pf[kf][1] = f2h2(sacc[2 * kf][2],     sacc[2 * kf][3]);
            pf[kf][2] = f2h2(sacc[2 * kf + 1][0], sacc[2 * kf + 1][1]);
            pf[kf][3] = f2h2(sacc[2 * kf + 1][2], sacc[2 * kf + 1][3]);
        }

        // ---- O += P V (V^T in smem: rows=d, cols=s) ----
        #pragma unroll
        for (int kf = 0; kf < 4; kf++) {
            #pragma unroll
            for (int ntp = 0; ntp < 4; ntp++) {
                uint32_t b0, b1, b2, b3;
                ldm_x4(b0, b1, b2, b3,
                       smem_u32(Vsb + (ntp * 16 + broff) * ALD + kf * 16 + bcoff));
                mma16816(oacc[2 * ntp],     pf[kf][0], pf[kf][1], pf[kf][2], pf[kf][3], b0, b1);
                mma16816(oacc[2 * ntp + 1], pf[kf][0], pf[kf][1], pf[kf][2], pf[kf][3], b2, b3);
            }
        }

        __syncthreads();
        if (kt + 2 < SEQ / 64) { loadKV(kt + 2, buf); cp_commit(); cp_wait<1>(); }
        else                   { cp_wait<0>(); }
        __syncthreads();
    }

    // ---- finalize: ctx[b*S + q][h*64 + d], fp16 ----
    float ilo = 1.0f / lrun_lo, ihi = 1.0f / lrun_hi;
    int rlo = q0 + wid * 16 + (lane >> 2);
    __half* outlo = g_ctx + ((size_t)(b * SEQ) + rlo) * D_MODEL + h * DH;
    __half* outhi = outlo + (size_t)8 * D_MODEL;
    #pragma unroll
    for (int nt = 0; nt < 8; nt++) {
        int d0 = nt * 8 + (lane & 3) * 2;
        *(__half2*)(outlo + d0) = __floats2half2_rn(oacc[nt][0] * ilo, oacc[nt][1] * ilo);
        *(__half2*)(outhi + d0) = __floats2half2_rn(oacc[nt][2] * ihi, oacc[nt][3] * ihi);
    }
}

// ---------------- launch ----------------
extern "C" void kernel_launch(void* const* d_in, const int* in_sizes, int n_in,
                              void* d_out, int out_size)
{
    const float* xq   = (const float*)d_in[0];
    const float* xk   = (const float*)d_in[1];
    const float* xv   = (const float*)d_in[2];
    const int*   mask = (const int*)  d_in[3];
    const float* Wq   = (const float*)d_in[4];
    const float* bq   = (const float*)d_in[5];
    const float* Wk   = (const float*)d_in[6];
    const float* bk   = (const float*)d_in[7];
    const float* Wv   = (const float*)d_in[8];
    const float* bv   = (const float*)d_in[9];
    const float* Wo   = (const float*)d_in[10];
    const float* bo   = (const float*)d_in[11];

    void *p_xq, *p_xk, *p_xv, *p_Wq, *p_Wk, *p_Wv, *p_Wo, *p_Q, *p_K, *p_V, *p_ctx;
    cudaGetSymbolAddress(&p_xq, g_xq);
    cudaGetSymbolAddress(&p_xk, g_xk);
    cudaGetSymbolAddress(&p_xv, g_xv);
    cudaGetSymbolAddress(&p_Wq, g_Wq);
    cudaGetSymbolAddress(&p_Wk, g_Wk);
    cudaGetSymbolAddress(&p_Wv, g_Wv);
    cudaGetSymbolAddress(&p_Wo, g_Wo);
    cudaGetSymbolAddress(&p_Q,  g_Q);
    cudaGetSymbolAddress(&p_K,  g_K);
    cudaGetSymbolAddress(&p_V,  g_V);
    cudaGetSymbolAddress(&p_ctx, g_ctx);

    cudaFuncSetAttribute(gemm2<0>, cudaFuncAttributeMaxDynamicSharedMemorySize, GEMM_SMEM);
    cudaFuncSetAttribute(gemm2<1>, cudaFuncAttributeMaxDynamicSharedMemorySize, GEMM_SMEM);
    cudaFuncSetAttribute(gemm2<2>, cudaFuncAttributeMaxDynamicSharedMemorySize, GEMM_SMEM);
    cudaFuncSetAttribute(attn2,    cudaFuncAttributeMaxDynamicSharedMemorySize, ATTN_SMEM);

    cvt_all<<<(M_TOT * D_MODEL + 255) / 256, 256>>>(xq, xk, xv, Wq, Wk, Wv, Wo);

    dim3 gg(D_MODEL / 128, M_TOT / 128);  // (8, 64)
    gemm2<1><<<gg, 256, GEMM_SMEM>>>((const __half*)p_xq, (const __half*)p_Wq, bq, p_Q, 0.125f);
    gemm2<1><<<gg, 256, GEMM_SMEM>>>((const __half*)p_xk, (const __half*)p_Wk, bk, p_K, 1.0f);
    gemm2<2><<<gg, 256, GEMM_SMEM>>>((const __half*)p_xv, (const __half*)p_Wv, bv, p_V, 1.0f);

    attn2<<<dim3(SEQ / 128, BATCH * NH), 256, ATTN_SMEM>>>(mask);

    gemm2<0><<<gg, 256, GEMM_SMEM>>>((const __half*)p_ctx, (const __half*)p_Wo, bo, d_out, 1.0f);
}